// round 1
// baseline (speedup 1.0000x reference)
#include <cuda_runtime.h>
#include <cstdint>

typedef unsigned long long ull;
#define FULLMASK 0xffffffffu

constexpr int MAX_ITER = 8192;
constexpr int NNODES   = MAX_ITER + 1;   // 8193
constexpr int K        = 32;             // iterations per block-phase
constexpr int NBLK     = MAX_ITER / K;   // 256
constexpr int NTHREADS = 1024;

// dynamic smem layout:
//   float2 nodes[8194]   (8193 + 1 pad for float4 tail, init to +inf sentinel)
//   float2 samps[8192]
//   ull    bests[32]
constexpr int NODES_PAD = 8194;
constexpr size_t SMEM_BYTES = (NODES_PAD + MAX_ITER) * sizeof(float2) + 32 * sizeof(ull);

__global__ void __launch_bounds__(NTHREADS, 1)
rrt_kernel(const float* __restrict__ state,
           const float* __restrict__ goal,
           const float* __restrict__ u,
           const float* __restrict__ r,
           float* __restrict__ out)
{
    extern __shared__ float2 smem[];
    float2* nodes_s = smem;                       // [0, 8194)
    float2* samps   = smem + NODES_PAD;           // [8194, 8194+8192)
    ull*    bests   = (ull*)(smem + NODES_PAD + MAX_ITER);

    const int tid  = threadIdx.x;
    const int lane = tid & 31;
    const int warp = tid >> 5;
    const float INF = __int_as_float(0x7f800000);

    // ---- init: sentinel nodes (inf => d2 = inf, excluded from argmin) ----
    for (int i = tid; i < NODES_PAD; i += NTHREADS)
        nodes_s[i] = make_float2(INF, INF);

    // ---- precompute all samples: where(u < 0.1, goal, r * 200) ----
    const float gx = goal[0], gy = goal[1];
    for (int i = tid; i < MAX_ITER; i += NTHREADS) {
        float ui = u[i];
        float sx = __fmul_rn(r[2 * i],     200.0f);
        float sy = __fmul_rn(r[2 * i + 1], 200.0f);
        if (ui < 0.1f) { sx = gx; sy = gy; }
        samps[i] = make_float2(sx, sy);
    }
    if (tid == 0) nodes_s[0] = make_float2(state[0], state[1]);
    __syncthreads();

    for (int b = 0; b < NBLK; b++) {
        const int i0 = b * K;   // nodes 0..i0 exist before this block

        // ============ parallel phase: warp w -> sample i0+w ============
        {
            const float2 s = samps[i0 + warp];
            float bd2 = INF;
            int   bidx = 0;
            // lane handles node pairs {2*lane + 64k, +1}; sentinel covers tail
            for (int idx = 2 * lane; idx <= i0; idx += 64) {
                float4 n = *reinterpret_cast<const float4*>(&nodes_s[idx]);
                float dxa = __fadd_rn(n.x, -s.x), dya = __fadd_rn(n.y, -s.y);
                float d2a = __fadd_rn(__fmul_rn(dxa, dxa), __fmul_rn(dya, dya));
                float dxb = __fadd_rn(n.z, -s.x), dyb = __fadd_rn(n.w, -s.y);
                float d2b = __fadd_rn(__fmul_rn(dxb, dxb), __fmul_rn(dyb, dyb));
                float m  = fminf(d2a, d2b);
                int   mi = (d2a <= d2b) ? idx : idx + 1;   // first-index tiebreak
                if (m < bd2) { bd2 = m; bidx = mi; }       // strict < keeps earliest
            }
            ull key = ((ull)__float_as_uint(bd2) << 32) | (uint32_t)bidx;
            #pragma unroll
            for (int o = 16; o > 0; o >>= 1) {
                ull other = __shfl_down_sync(FULLMASK, key, o);
                key = (other < key) ? other : key;         // min(d2), then min(idx)
            }
            if (lane == 0) bests[warp] = key;
        }
        __syncthreads();

        // ============ serial phase: warp 0, lane j owns sample i0+j ============
        if (warp == 0) {
            ull key = bests[lane];
            float2 f = nodes_s[(uint32_t)key];             // prefetch best from-node
            float fx = f.x, fy = f.y;
            float2 s = samps[i0 + lane];
            const float sx = s.x, sy = s.y;
            #pragma unroll
            for (int l = 0; l < K; l++) {
                // broadcast lane l's finalized (d2, from-node); all lanes compute
                // the new node redundantly (no STS/LDS/syncwarp in the chain)
                float d2l = __uint_as_float(__shfl_sync(FULLMASK, (uint32_t)(key >> 32), l));
                float fxl = __shfl_sync(FULLMASK, fx, l);
                float fyl = __shfl_sync(FULLMASK, fy, l);
                float sxl = __shfl_sync(FULLMASK, sx, l);
                float syl = __shfl_sync(FULLMASK, sy, l);

                float dist  = __fsqrt_rn(__fadd_rn(d2l, 1e-12f));
                float q     = __fdiv_rn(5.0f, dist);
                float scale = (dist > 5.0f) ? q : 1.0f;
                float nx = __fadd_rn(fxl, __fmul_rn(__fadd_rn(sxl, -fxl), scale));
                float ny = __fadd_rn(fyl, __fmul_rn(__fadd_rn(syl, -fyl), scale));
                int nidx = i0 + l + 1;

                if (lane == 0) nodes_s[nidx] = make_float2(nx, ny); // for next block
                if (lane > l) {                                      // fixup later samples
                    float dx  = __fadd_rn(nx, -sx), dy = __fadd_rn(ny, -sy);
                    float cd2 = __fadd_rn(__fmul_rn(dx, dx), __fmul_rn(dy, dy));
                    ull ck = ((ull)__float_as_uint(cd2) << 32) | (uint32_t)nidx;
                    if (ck < key) { key = ck; fx = nx; fy = ny; }
                }
            }
        }
        __syncthreads();
    }

    // ---- write out nodes (8193 x 2 floats) ----
    const float* ns = reinterpret_cast<const float*>(nodes_s);
    for (int i = tid; i < 2 * NNODES; i += NTHREADS)
        out[i] = ns[i];
}

extern "C" void kernel_launch(void* const* d_in, const int* in_sizes, int n_in,
                              void* d_out, int out_size)
{
    const float* state = (const float*)d_in[0];
    const float* goal  = (const float*)d_in[1];
    const float* u     = (const float*)d_in[2];
    const float* r     = (const float*)d_in[3];
    float* out = (float*)d_out;

    cudaFuncSetAttribute(rrt_kernel,
                         cudaFuncAttributeMaxDynamicSharedMemorySize,
                         (int)SMEM_BYTES);
    rrt_kernel<<<1, NTHREADS, SMEM_BYTES>>>(state, goal, u, r, out);
}

// round 3
// speedup vs baseline: 2.2161x; 2.2161x over previous
#include <cuda_runtime.h>
#include <cstdint>

typedef unsigned long long ull;
#define FULLMASK 0xffffffffu

constexpr int MAX_ITER = 8192;
constexpr int NNODES   = MAX_ITER + 1;   // 8193
constexpr int K        = 32;             // iterations per block-phase
constexpr int NBLK     = MAX_ITER / K;   // 256
constexpr int NTHREADS = 1024;
constexpr int CSIZE    = 8;              // cluster size

// per-CTA dynamic smem layout (identical in every CTA):
//   float2 nodes[8194]   (8193 + pad for float4 tail; init +inf sentinel)
//   float2 samps[8192]
//   ull    bests[8][32]  (only CTA 0's copy is read)
constexpr int NODES_PAD = 8194;
constexpr size_t BESTS_OFF  = (size_t)(NODES_PAD + MAX_ITER) * sizeof(float2);
constexpr size_t SMEM_BYTES = BESTS_OFF + CSIZE * 32 * sizeof(ull);

__device__ __forceinline__ uint32_t smem_u32(const void* p) {
    return (uint32_t)__cvta_generic_to_shared(p);
}
__device__ __forceinline__ uint32_t my_ctarank() {
    uint32_t r; asm("mov.u32 %0, %%cluster_ctarank;" : "=r"(r)); return r;
}
__device__ __forceinline__ void sts_cluster_u64(uint32_t laddr, uint32_t rank, ull v) {
    uint32_t raddr;
    asm volatile("mapa.shared::cluster.u32 %0, %1, %2;" : "=r"(raddr) : "r"(laddr), "r"(rank));
    asm volatile("st.shared::cluster.u64 [%0], %1;" :: "r"(raddr), "l"(v) : "memory");
}
#define CLUSTER_ARRIVE() asm volatile("barrier.cluster.arrive.aligned;" ::: "memory")
#define CLUSTER_WAIT()   asm volatile("barrier.cluster.wait.aligned;"   ::: "memory")

__global__ void __launch_bounds__(NTHREADS, 1) __cluster_dims__(CSIZE, 1, 1)
rrt_kernel(const float* __restrict__ state,
           const float* __restrict__ goal,
           const float* __restrict__ u,
           const float* __restrict__ r,
           float* __restrict__ out)
{
    extern __shared__ float2 smem[];
    float2* nodes_s = smem;                       // [0, 8194)
    float2* samps   = smem + NODES_PAD;           // [8194, +8192)
    ull (*bests)[32] = (ull (*)[32])((char*)smem + BESTS_OFF);   // [8][32]

    const int tid   = threadIdx.x;
    const int lane  = tid & 31;
    const int warp  = tid >> 5;
    const uint32_t crank = my_ctarank();
    const float INF = __int_as_float(0x7f800000);

    // ---- init (per CTA): sentinel nodes, samples, start node ----
    for (int i = tid; i < NODES_PAD; i += NTHREADS)
        nodes_s[i] = make_float2(INF, INF);
    const float gx = goal[0], gy = goal[1];
    for (int i = tid; i < MAX_ITER; i += NTHREADS) {
        float ui = u[i];
        float sx = __fmul_rn(r[2 * i],     200.0f);
        float sy = __fmul_rn(r[2 * i + 1], 200.0f);
        if (ui < 0.1f) { sx = gx; sy = gy; }
        samps[i] = make_float2(sx, sy);
    }
    if (tid == 0) nodes_s[0] = make_float2(state[0], state[1]);
    __syncthreads();

    const uint32_t bests_laddr = smem_u32(&bests[crank][warp]);

    for (int b = 0; b < NBLK; b++) {
        const int i0 = b * K;   // nodes 0..i0 exist before this block

        // ===== parallel phase: warp w -> sample i0+w; tiles striped over CTAs =====
        {
            const float2 s = samps[i0 + warp];
            float bd2 = INF;
            int   bidx = 0;
            for (int t = crank; t * 64 <= i0; t += CSIZE) {
                int idx = 64 * t + 2 * lane;
                float4 n = *reinterpret_cast<const float4*>(&nodes_s[idx]);
                float dxa = __fadd_rn(n.x, -s.x), dya = __fadd_rn(n.y, -s.y);
                float d2a = __fadd_rn(__fmul_rn(dxa, dxa), __fmul_rn(dya, dya));
                float dxb = __fadd_rn(n.z, -s.x), dyb = __fadd_rn(n.w, -s.y);
                float d2b = __fadd_rn(__fmul_rn(dxb, dxb), __fmul_rn(dyb, dyb));
                float m  = fminf(d2a, d2b);
                int   mi = (d2a <= d2b) ? idx : idx + 1;   // first-index tiebreak
                if (m < bd2) { bd2 = m; bidx = mi; }
            }
            ull key = ((ull)__float_as_uint(bd2) << 32) | (uint32_t)bidx;
            #pragma unroll
            for (int o = 16; o > 0; o >>= 1) {
                ull other = __shfl_down_sync(FULLMASK, key, o);
                key = (other < key) ? other : key;
            }
            if (lane == 0) sts_cluster_u64(bests_laddr, 0, key);  // -> CTA 0
        }
        CLUSTER_ARRIVE();   // release partial keys
        CLUSTER_WAIT();

        // ===== serial phase: CTA 0, warp 0; lane j owns sample i0+j =====
        if (crank == 0 && warp == 0) {
            // reduce partials across 8 CTAs
            ull key = bests[0][lane];
            #pragma unroll
            for (int c = 1; c < CSIZE; c++) {
                ull k2 = bests[c][lane];
                key = (k2 < key) ? k2 : key;
            }
            const float2 s = samps[i0 + lane];
            const float sx = s.x, sy = s.y;
            float2 f = nodes_s[(uint32_t)key];
            // eagerly compute this lane's candidate new node
            float d2   = __uint_as_float((uint32_t)(key >> 32));
            float dist = __fsqrt_rn(__fadd_rn(d2, 1e-12f));
            float q    = __fdiv_rn(5.0f, dist);
            float sc   = (dist > 5.0f) ? q : 1.0f;
            float nx = __fadd_rn(f.x, __fmul_rn(__fadd_rn(sx, -f.x), sc));
            float ny = __fadd_rn(f.y, __fmul_rn(__fadd_rn(sy, -f.y), sc));

            #pragma unroll
            for (int l = 0; l < K; l++) {
                // lane l's nx,ny are final (only fixups at iters < l touch it)
                float nxl = __shfl_sync(FULLMASK, nx, l);
                float nyl = __shfl_sync(FULLMASK, ny, l);
                int nidx = i0 + l + 1;
                if (lane == l) nodes_s[nidx] = make_float2(nx, ny);
                if (lane > l) {
                    float dx  = __fadd_rn(nxl, -sx), dy = __fadd_rn(nyl, -sy);
                    float cd2 = __fadd_rn(__fmul_rn(dx, dx), __fmul_rn(dy, dy));
                    ull ck = ((ull)__float_as_uint(cd2) << 32) | (uint32_t)nidx;
                    if (ck < key) {
                        key = ck;
                        // recompute candidate new node from the updated parent
                        float dist2 = __fsqrt_rn(__fadd_rn(cd2, 1e-12f));
                        float q2    = __fdiv_rn(5.0f, dist2);
                        float sc2   = (dist2 > 5.0f) ? q2 : 1.0f;
                        nx = __fadd_rn(nxl, __fmul_rn(__fadd_rn(sx, -nxl), sc2));
                        ny = __fadd_rn(nyl, __fmul_rn(__fadd_rn(sy, -nyl), sc2));
                    }
                }
            }
            // broadcast the 32 new nodes to peers 1..7 (lane j holds node i0+1+j)
            ull packed = ((ull)__float_as_uint(ny) << 32) | __float_as_uint(nx);
            uint32_t laddr = smem_u32(&nodes_s[i0 + 1 + lane]);
            #pragma unroll
            for (int c = 1; c < CSIZE; c++)
                sts_cluster_u64(laddr, c, packed);
        }
        CLUSTER_ARRIVE();   // release new nodes
        CLUSTER_WAIT();
    }

    // ---- CTA 0 writes out nodes (8193 x 2 floats) ----
    if (crank == 0) {
        const float* ns = reinterpret_cast<const float*>(nodes_s);
        for (int i = tid; i < 2 * NNODES; i += NTHREADS)
            out[i] = ns[i];
    }
}

extern "C" void kernel_launch(void* const* d_in, const int* in_sizes, int n_in,
                              void* d_out, int out_size)
{
    const float* state = (const float*)d_in[0];
    const float* goal  = (const float*)d_in[1];
    const float* u     = (const float*)d_in[2];
    const float* r     = (const float*)d_in[3];
    float* out = (float*)d_out;

    cudaFuncSetAttribute(rrt_kernel,
                         cudaFuncAttributeMaxDynamicSharedMemorySize,
                         (int)SMEM_BYTES);
    rrt_kernel<<<CSIZE, NTHREADS, SMEM_BYTES>>>(state, goal, u, r, out);
}

// round 4
// speedup vs baseline: 2.4668x; 1.1131x over previous
#include <cuda_runtime.h>
#include <cstdint>

typedef unsigned long long ull;
#define FULLMASK 0xffffffffu

constexpr int MAX_ITER = 8192;
constexpr int NNODES   = MAX_ITER + 1;   // 8193
constexpr int K        = 32;             // iterations per block
constexpr int NBLK     = MAX_ITER / K;   // 256
constexpr int NTHREADS = 1024;           // 32 warps
constexpr int CSIZE    = 8;              // cluster size
constexpr int SERIAL_WARP = 31;          // highest wid -> arbiter priority
constexpr int AUX_WARP    = 30;          // scans serial-warp's sample too

constexpr int NODES_PAD = 8194;
// per-CTA smem layout (bytes):
//   nodes  : float2[8194]
//   samps  : float2[8192]
//   bests  : ull[2][8][32]   (double-buffered by block parity)
//   keyaux : ull[2]          (scan partial for sample 31 of each block)
//   mbars  : ull[2]          (mb_nodes, mb_bests)
constexpr size_t OFF_SAMPS  = (size_t)NODES_PAD * sizeof(float2);
constexpr size_t OFF_BESTS  = OFF_SAMPS + (size_t)MAX_ITER * sizeof(float2);
constexpr size_t OFF_KEYAUX = OFF_BESTS + 2 * CSIZE * 32 * sizeof(ull);
constexpr size_t OFF_MBARS  = OFF_KEYAUX + 2 * sizeof(ull);
constexpr size_t SMEM_BYTES = OFF_MBARS + 2 * sizeof(ull);

constexpr ull KEY_INF = ((ull)0x7f800000u << 32);

__device__ __forceinline__ uint32_t smem_u32(const void* p) {
    return (uint32_t)__cvta_generic_to_shared(p);
}
__device__ __forceinline__ uint32_t my_ctarank() {
    uint32_t r; asm("mov.u32 %0, %%cluster_ctarank;" : "=r"(r)); return r;
}
__device__ __forceinline__ uint32_t mapa_u32(uint32_t laddr, uint32_t rank) {
    uint32_t r; asm("mapa.shared::cluster.u32 %0, %1, %2;" : "=r"(r) : "r"(laddr), "r"(rank));
    return r;
}
__device__ __forceinline__ void st_cluster_u64(uint32_t raddr, ull v) {
    asm volatile("st.shared::cluster.u64 [%0], %1;" :: "r"(raddr), "l"(v) : "memory");
}
__device__ __forceinline__ void mbar_init(uint32_t a, uint32_t cnt) {
    asm volatile("mbarrier.init.shared.b64 [%0], %1;" :: "r"(a), "r"(cnt) : "memory");
}
__device__ __forceinline__ void mbar_arrive_cta(uint32_t a) {
    asm volatile("mbarrier.arrive.release.cta.shared::cta.b64 _, [%0];" :: "r"(a) : "memory");
}
__device__ __forceinline__ void mbar_arrive_cluster_remote(uint32_t raddr) {
    asm volatile("mbarrier.arrive.release.cluster.shared::cluster.b64 _, [%0];"
                 :: "r"(raddr) : "memory");
}
__device__ __forceinline__ void mbar_wait_cta(uint32_t a, uint32_t phase) {
    asm volatile(
        "{\n\t.reg .pred P;\n\t"
        "WL_%=:\n\t"
        "mbarrier.try_wait.parity.acquire.cta.shared::cta.b64 P, [%0], %1, 0x989680;\n\t"
        "@P bra.uni WD_%=;\n\t"
        "bra.uni WL_%=;\n\t"
        "WD_%=:\n\t}"
        :: "r"(a), "r"(phase) : "memory");
}
__device__ __forceinline__ void mbar_wait_cluster(uint32_t a, uint32_t phase) {
    asm volatile(
        "{\n\t.reg .pred P;\n\t"
        "WL_%=:\n\t"
        "mbarrier.try_wait.parity.acquire.cluster.shared::cta.b64 P, [%0], %1, 0x989680;\n\t"
        "@P bra.uni WD_%=;\n\t"
        "bra.uni WL_%=;\n\t"
        "WD_%=:\n\t}"
        :: "r"(a), "r"(phase) : "memory");
}
#define CLUSTER_ARRIVE() asm volatile("barrier.cluster.arrive.aligned;" ::: "memory")
#define CLUSTER_WAIT()   asm volatile("barrier.cluster.wait.aligned;"   ::: "memory")

// per-lane scan partial for sample s over tiles t = crank, crank+8, ... with 64t+63 <= 32b
__device__ __forceinline__ ull scan_partial(const float2* __restrict__ nodes_s,
                                            float2 s, int b, int crank, int lane)
{
    const float INF = __int_as_float(0x7f800000);
    float bd2 = INF; int bidx = 0;
    for (int t = crank; 64 * t + 63 <= 32 * b; t += CSIZE) {
        int idx = 64 * t + 2 * lane;
        float4 n = *reinterpret_cast<const float4*>(&nodes_s[idx]);
        float dxa = __fadd_rn(n.x, -s.x), dya = __fadd_rn(n.y, -s.y);
        float d2a = __fadd_rn(__fmul_rn(dxa, dxa), __fmul_rn(dya, dya));
        float dxb = __fadd_rn(n.z, -s.x), dyb = __fadd_rn(n.w, -s.y);
        float d2b = __fadd_rn(__fmul_rn(dxb, dxb), __fmul_rn(dyb, dyb));
        float m  = fminf(d2a, d2b);
        int   mi = (d2a <= d2b) ? idx : idx + 1;     // first-index tiebreak in pair
        if (m < bd2) { bd2 = m; bidx = mi; }         // strict < keeps earliest
    }
    return ((ull)__float_as_uint(bd2) << 32) | (uint32_t)bidx;
}

__global__ void __launch_bounds__(NTHREADS, 1) __cluster_dims__(CSIZE, 1, 1)
rrt_kernel(const float* __restrict__ state,
           const float* __restrict__ goal,
           const float* __restrict__ u,
           const float* __restrict__ r,
           float* __restrict__ out)
{
    extern __shared__ char smem_raw[];
    float2* nodes_s = (float2*)smem_raw;
    float2* samps   = (float2*)(smem_raw + OFF_SAMPS);
    ull (*bests)[CSIZE][32] = (ull (*)[CSIZE][32])(smem_raw + OFF_BESTS);
    ull* keyaux = (ull*)(smem_raw + OFF_KEYAUX);
    ull* mbars  = (ull*)(smem_raw + OFF_MBARS);

    const int tid  = threadIdx.x;
    const int lane = tid & 31;
    const int warp = tid >> 5;
    const uint32_t crank = my_ctarank();
    const float INF = __int_as_float(0x7f800000);

    const uint32_t mb_nodes = smem_u32(&mbars[0]);
    const uint32_t mb_bests = smem_u32(&mbars[1]);

    // ---- init: sentinels, samples, node0, mbarriers ----
    for (int i = tid; i < NODES_PAD; i += NTHREADS)
        nodes_s[i] = make_float2(INF, INF);
    const float gx = goal[0], gy = goal[1];
    for (int i = tid; i < MAX_ITER; i += NTHREADS) {
        float ui = u[i];
        float sx = __fmul_rn(r[2 * i],     200.0f);
        float sy = __fmul_rn(r[2 * i + 1], 200.0f);
        if (ui < 0.1f) { sx = gx; sy = gy; }
        samps[i] = make_float2(sx, sy);
    }
    if (tid == 0) {
        nodes_s[0] = make_float2(state[0], state[1]);
        mbar_init(mb_nodes, 64);    // 32 lanes serial warp + 32 lanes aux warp
        mbar_init(mb_bests, 256);   // 8 CTAs x 32 warps
    }
    __syncthreads();
    CLUSTER_ARRIVE();
    CLUSTER_WAIT();

    ull pkey = KEY_INF;   // per-lane scan partial for this warp's next sample

    for (int b = 0; b < NBLK; b++) {
        // ---- wait for nodes of block b-1 (and keyaux) ----
        if (b > 0) mbar_wait_cta(mb_nodes, (b - 1) & 1);

        // ---- delta phase: sample 32b+warp over W(b)=[32b-95, 32b] ----
        const float2 s = samps[32 * b + warp];
        ull key = pkey;
        if (warp == SERIAL_WARP && lane == 0 && b > 0) {
            ull ka = keyaux[b & 1];
            key = (ka < key) ? ka : key;
        }
        #pragma unroll
        for (int m = 0; m < 3; m++) {
            int idx = 32 * b - 95 + 32 * m + lane;
            if (idx >= 0) {
                float2 n = nodes_s[idx];
                float dx = __fadd_rn(n.x, -s.x), dy = __fadd_rn(n.y, -s.y);
                float d2 = __fadd_rn(__fmul_rn(dx, dx), __fmul_rn(dy, dy));
                ull ck = ((ull)__float_as_uint(d2) << 32) | (uint32_t)idx;
                key = (ck < key) ? ck : key;
            }
        }
        #pragma unroll
        for (int o = 16; o > 0; o >>= 1) {     // butterfly: all lanes get min
            ull o2 = __shfl_xor_sync(FULLMASK, key, o);
            key = (o2 < key) ? o2 : key;
        }
        // ---- all-to-all send: lane c -> CTA c ----
        {
            uint32_t bl = smem_u32(&bests[b & 1][crank][warp]);
            if (lane < CSIZE) {
                st_cluster_u64(mapa_u32(bl, (uint32_t)lane), key);
                mbar_arrive_cluster_remote(mapa_u32(mb_bests, (uint32_t)lane));
            }
        }

        if (warp == SERIAL_WARP) {
            // ---- serial phase (redundant in every CTA) ----
            mbar_wait_cluster(mb_bests, b & 1);
            ull kk = bests[b & 1][0][lane];
            #pragma unroll
            for (int c = 1; c < CSIZE; c++) {
                ull k2 = bests[b & 1][c][lane];
                kk = (k2 < kk) ? k2 : kk;
            }
            const float2 s2 = samps[32 * b + lane];
            const float sx = s2.x, sy = s2.y;
            float kd2 = __uint_as_float((uint32_t)(kk >> 32));
            float2 f  = nodes_s[(uint32_t)kk];
            float dist = __fsqrt_rn(__fadd_rn(kd2, 1e-12f));
            float q    = __fdiv_rn(5.0f, dist);
            float sc   = (dist > 5.0f) ? q : 1.0f;
            float nx = __fadd_rn(f.x, __fmul_rn(__fadd_rn(sx, -f.x), sc));
            float ny = __fadd_rn(f.y, __fmul_rn(__fadd_rn(sy, -f.y), sc));
            #pragma unroll
            for (int l = 0; l < K; l++) {
                float nxl = __shfl_sync(FULLMASK, nx, l);
                float nyl = __shfl_sync(FULLMASK, ny, l);
                if (lane == l) nodes_s[32 * b + 1 + l] = make_float2(nx, ny);
                float dx  = __fadd_rn(sx, -nxl);
                float dy  = __fadd_rn(sy, -nyl);
                float cd2 = __fadd_rn(__fmul_rn(dx, dx), __fmul_rn(dy, dy));
                if (lane > l && cd2 < kd2) {           // strict <: earliest index wins
                    kd2 = cd2;
                    float d2e = __fsqrt_rn(__fadd_rn(cd2, 1e-12f));
                    float q2  = __fdiv_rn(5.0f, d2e);
                    float sc2 = (d2e > 5.0f) ? q2 : 1.0f;
                    nx = __fadd_rn(nxl, __fmul_rn(dx, sc2));
                    ny = __fadd_rn(nyl, __fmul_rn(dy, sc2));
                }
            }
            if (b < NBLK - 1) mbar_arrive_cta(mb_nodes);   // all 32 lanes
        } else if (b < NBLK - 1) {
            // ---- overlap scans for block b+1 (run during serial phase b) ----
            if (warp == AUX_WARP) {
                // serial-warp's sample first, then arrive early
                ull ak = scan_partial(nodes_s, samps[32 * (b + 1) + SERIAL_WARP],
                                      b, (int)crank, lane);
                #pragma unroll
                for (int o = 16; o > 0; o >>= 1) {
                    ull o2 = __shfl_xor_sync(FULLMASK, ak, o);
                    ak = (o2 < ak) ? o2 : ak;
                }
                if (lane == 0) keyaux[(b + 1) & 1] = ak;
                mbar_arrive_cta(mb_nodes);                 // all 32 lanes
            }
            pkey = scan_partial(nodes_s, samps[32 * (b + 1) + warp],
                                b, (int)crank, lane);
        }
    }

    __syncthreads();
    CLUSTER_ARRIVE();
    CLUSTER_WAIT();

    // ---- rank 0 writes out nodes (8193 x 2 floats, all local) ----
    if (crank == 0) {
        const float* ns = reinterpret_cast<const float*>(nodes_s);
        for (int i = tid; i < 2 * NNODES; i += NTHREADS)
            out[i] = ns[i];
    }
}

extern "C" void kernel_launch(void* const* d_in, const int* in_sizes, int n_in,
                              void* d_out, int out_size)
{
    const float* state = (const float*)d_in[0];
    const float* goal  = (const float*)d_in[1];
    const float* u     = (const float*)d_in[2];
    const float* r     = (const float*)d_in[3];
    float* out = (float*)d_out;

    cudaFuncSetAttribute(rrt_kernel,
                         cudaFuncAttributeMaxDynamicSharedMemorySize,
                         (int)SMEM_BYTES);
    rrt_kernel<<<CSIZE, NTHREADS, SMEM_BYTES>>>(state, goal, u, r, out);
}

// round 5
// speedup vs baseline: 2.9338x; 1.1893x over previous
#include <cuda_runtime.h>
#include <cstdint>

typedef unsigned long long ull;
#define FULLMASK 0xffffffffu

constexpr int MAX_ITER = 8192;
constexpr int NNODES   = MAX_ITER + 1;   // 8193
constexpr int NBLK     = 256;            // 32 iterations per block
constexpr int NTHREADS = 1024;           // 32 warps
constexpr int CSIZE    = 8;
constexpr int SERIAL_WARP = 31;

constexpr int NODES_PAD = 8194;
constexpr int NSLOT_PAD = 34;            // slots 0..30 = samples, 31/32 = sample-31 halves

// per-CTA smem layout:
//   nodes float2[8194] | samps float2[8192] | bests ull[4][8][34] | keys ull[2][32]
//   cand float2[32]    | mbars ull[6] (0=nodes, 1=keys, 2..5=bests objs)
constexpr size_t OFF_SAMPS = (size_t)NODES_PAD * sizeof(float2);
constexpr size_t OFF_BESTS = OFF_SAMPS + (size_t)MAX_ITER * sizeof(float2);
constexpr size_t OFF_KEYS  = OFF_BESTS + 4ull * CSIZE * NSLOT_PAD * sizeof(ull);
constexpr size_t OFF_CAND  = OFF_KEYS + 2ull * 32 * sizeof(ull);
constexpr size_t OFF_MBARS = OFF_CAND + 32ull * sizeof(float2);
constexpr size_t SMEM_BYTES = OFF_MBARS + 6ull * sizeof(ull);

constexpr ull KEY_INF = ((ull)0x7f800000u << 32);

__device__ __forceinline__ uint32_t smem_u32(const void* p) {
    return (uint32_t)__cvta_generic_to_shared(p);
}
__device__ __forceinline__ uint32_t my_ctarank() {
    uint32_t r; asm("mov.u32 %0, %%cluster_ctarank;" : "=r"(r)); return r;
}
__device__ __forceinline__ uint32_t mapa_u32(uint32_t laddr, uint32_t rank) {
    uint32_t r; asm("mapa.shared::cluster.u32 %0, %1, %2;" : "=r"(r) : "r"(laddr), "r"(rank));
    return r;
}
__device__ __forceinline__ void st_cluster_u64(uint32_t raddr, ull v) {
    asm volatile("st.shared::cluster.u64 [%0], %1;" :: "r"(raddr), "l"(v) : "memory");
}
__device__ __forceinline__ void mbar_init(uint32_t a, uint32_t cnt) {
    asm volatile("mbarrier.init.shared.b64 [%0], %1;" :: "r"(a), "r"(cnt) : "memory");
}
__device__ __forceinline__ void mbar_arrive_cta(uint32_t a) {
    asm volatile("mbarrier.arrive.release.cta.shared::cta.b64 _, [%0];" :: "r"(a) : "memory");
}
__device__ __forceinline__ void mbar_arrive_cluster_remote(uint32_t raddr) {
    asm volatile("mbarrier.arrive.release.cluster.shared::cluster.b64 _, [%0];"
                 :: "r"(raddr) : "memory");
}
__device__ __forceinline__ void mbar_wait_cta(uint32_t a, uint32_t phase) {
    asm volatile(
        "{\n\t.reg .pred P;\n\t"
        "WL_%=:\n\t"
        "mbarrier.try_wait.parity.acquire.cta.shared::cta.b64 P, [%0], %1, 0x989680;\n\t"
        "@P bra.uni WD_%=;\n\t"
        "bra.uni WL_%=;\n\t"
        "WD_%=:\n\t}"
        :: "r"(a), "r"(phase) : "memory");
}
__device__ __forceinline__ void mbar_wait_cluster(uint32_t a, uint32_t phase) {
    asm volatile(
        "{\n\t.reg .pred P;\n\t"
        "WL_%=:\n\t"
        "mbarrier.try_wait.parity.acquire.cluster.shared::cta.b64 P, [%0], %1, 0x989680;\n\t"
        "@P bra.uni WD_%=;\n\t"
        "bra.uni WL_%=;\n\t"
        "WD_%=:\n\t}"
        :: "r"(a), "r"(phase) : "memory");
}
#define CLUSTER_ARRIVE() asm volatile("barrier.cluster.arrive.aligned;" ::: "memory")
#define CLUSTER_WAIT()   asm volatile("barrier.cluster.wait.aligned;"   ::: "memory")

__device__ __forceinline__ ull bfly_min(ull key) {
    #pragma unroll
    for (int o = 16; o > 0; o >>= 1) {
        ull other = __shfl_xor_sync(FULLMASK, key, o);
        key = (other < key) ? other : key;
    }
    return key;
}

// exact-rounding steer: new = from + (sample-from)*scale, scale = dist>5 ? 5/dist : 1
__device__ __forceinline__ void steer(float fx, float fy, float sx, float sy, float d2,
                                      float& ox, float& oy) {
    float dist = __fsqrt_rn(__fadd_rn(d2, 1e-12f));
    float q    = __fdiv_rn(5.0f, dist);
    float sc   = (dist > 5.0f) ? q : 1.0f;
    ox = __fadd_rn(fx, __fmul_rn(__fadd_rn(sx, -fx), sc));
    oy = __fadd_rn(fy, __fmul_rn(__fadd_rn(sy, -fy), sc));
}

// per-lane scan partial over tiles t = t0, t0+tstep, ... while 64t <= bound.
// sentinel (+inf) nodes make over-reads harmless.
__device__ __forceinline__ ull scan_part(const float2* __restrict__ nodes_s, float2 s,
                                         int bound, int t0, int tstep, int lane) {
    const float INF = __int_as_float(0x7f800000);
    float bd2 = INF; int bidx = 0;
    for (int t = t0; 64 * t <= bound; t += tstep) {
        int idx = 64 * t + 2 * lane;
        float4 n = *reinterpret_cast<const float4*>(&nodes_s[idx]);
        float dxa = __fadd_rn(n.x, -s.x), dya = __fadd_rn(n.y, -s.y);
        float d2a = __fadd_rn(__fmul_rn(dxa, dxa), __fmul_rn(dya, dya));
        float dxb = __fadd_rn(n.z, -s.x), dyb = __fadd_rn(n.w, -s.y);
        float d2b = __fadd_rn(__fmul_rn(dxb, dxb), __fmul_rn(dyb, dyb));
        float m  = fminf(d2a, d2b);
        int   mi = (d2a <= d2b) ? idx : idx + 1;     // first-index tiebreak in pair
        if (m < bd2) { bd2 = m; bidx = mi; }         // strict <: earliest kept
    }
    return ((ull)__float_as_uint(bd2) << 32) | (uint32_t)bidx;
}

__global__ void __launch_bounds__(NTHREADS, 1) __cluster_dims__(CSIZE, 1, 1)
rrt_kernel(const float* __restrict__ state,
           const float* __restrict__ goal,
           const float* __restrict__ u,
           const float* __restrict__ r,
           float* __restrict__ out)
{
    extern __shared__ char smem_raw[];
    float2* nodes_s = (float2*)smem_raw;
    float2* samps   = (float2*)(smem_raw + OFF_SAMPS);
    ull (*bests)[CSIZE][NSLOT_PAD] = (ull (*)[CSIZE][NSLOT_PAD])(smem_raw + OFF_BESTS);
    ull (*keys)[32] = (ull (*)[32])(smem_raw + OFF_KEYS);
    float2* cand    = (float2*)(smem_raw + OFF_CAND);
    ull* mbars      = (ull*)(smem_raw + OFF_MBARS);

    const int tid  = threadIdx.x;
    const int lane = tid & 31;
    const int warp = tid >> 5;
    const uint32_t crank = my_ctarank();
    const float INF = __int_as_float(0x7f800000);

    const uint32_t mb_nodes = smem_u32(&mbars[0]);
    const uint32_t mb_keys  = smem_u32(&mbars[1]);
    const uint32_t mb_bests0 = smem_u32(&mbars[2]);   // objects 0..3 at +8*obj

    // ---- init ----
    for (int i = tid; i < NODES_PAD; i += NTHREADS)
        nodes_s[i] = make_float2(INF, INF);
    const float gx = goal[0], gy = goal[1];
    for (int i = tid; i < MAX_ITER; i += NTHREADS) {
        float ui = u[i];
        float sx = __fmul_rn(r[2 * i],     200.0f);
        float sy = __fmul_rn(r[2 * i + 1], 200.0f);
        if (ui < 0.1f) { sx = gx; sy = gy; }
        samps[i] = make_float2(sx, sy);
    }
    if (tid == 0) {
        nodes_s[0] = make_float2(state[0], state[1]);
        mbar_init(mb_nodes, 32);                   // serial warp lanes
        mbar_init(mb_keys, 31);                    // scan warps' lane-0
        for (int o = 0; o < 4; o++)                // 33 slots x 8 src CTAs
            mbar_init(mb_bests0 + 8 * o, 33 * CSIZE);
    }
    __syncthreads();
    CLUSTER_ARRIVE();
    CLUSTER_WAIT();

    for (int b = 0; b < NBLK; b++) {
        if (b > 0) {
            if (warp != SERIAL_WARP) mbar_wait_cta(mb_nodes, (b - 1) & 1);
            mbar_wait_cluster(mb_bests0 + 8 * ((b - 1) & 3), ((b - 1) >> 2) & 1);
        }

        if (warp != SERIAL_WARP) {
            // ===== delta + merge for sample 32b+warp =====
            const float2 s = samps[32 * b + warp];
            ull key = KEY_INF;
            if (b > 0 && lane < CSIZE) key = bests[(b - 1) & 3][lane][warp];
            int idx = 32 * b - 31 + lane;
            if (idx >= 0) {
                float2 n = nodes_s[idx];
                float dx = __fadd_rn(n.x, -s.x), dy = __fadd_rn(n.y, -s.y);
                float d2 = __fadd_rn(__fmul_rn(dx, dx), __fmul_rn(dy, dy));
                ull ck = ((ull)__float_as_uint(d2) << 32) | (uint32_t)idx;
                key = (ck < key) ? ck : key;
            }
            key = bfly_min(key);
            if (lane == 0) keys[b & 1][warp] = key;
            if (lane == 0) mbar_arrive_cta(mb_keys);

            // ===== overlapped scan + cross-CTA send for block b+1 =====
            if (b < NBLK - 1) {
                const int obj = b & 3;
                ull pk = scan_part(nodes_s, samps[32 * (b + 1) + warp],
                                   32 * b, (int)crank, CSIZE, lane);
                pk = bfly_min(pk);
                if (lane < CSIZE) {
                    uint32_t la = smem_u32(&bests[obj][crank][warp]);
                    st_cluster_u64(mapa_u32(la, (uint32_t)lane), pk);
                    mbar_arrive_cluster_remote(mapa_u32(mb_bests0 + 8 * obj, (uint32_t)lane));
                }
                if (warp == 29 || warp == 30) {       // sample 31 split in halves
                    int t0 = (warp == 29) ? (int)crank : (int)crank + CSIZE;
                    ull pk2 = scan_part(nodes_s, samps[32 * (b + 1) + 31],
                                        32 * b, t0, 2 * CSIZE, lane);
                    pk2 = bfly_min(pk2);
                    int slot = (warp == 29) ? 31 : 32;
                    if (lane < CSIZE) {
                        uint32_t la = smem_u32(&bests[obj][crank][slot]);
                        st_cluster_u64(mapa_u32(la, (uint32_t)lane), pk2);
                        mbar_arrive_cluster_remote(mapa_u32(mb_bests0 + 8 * obj, (uint32_t)lane));
                    }
                }
            }
        } else {
            // ===== serial warp =====
            // delta + merge for sample 32b+31 (slots 31,32)
            const float2 s = samps[32 * b + 31];
            ull key = KEY_INF;
            if (b > 0) {
                if (lane < CSIZE)            key = bests[(b - 1) & 3][lane][31];
                else if (lane < 2 * CSIZE)   key = bests[(b - 1) & 3][lane - CSIZE][32];
            }
            int idx = 32 * b - 31 + lane;
            if (idx >= 0) {
                float2 n = nodes_s[idx];
                float dx = __fadd_rn(n.x, -s.x), dy = __fadd_rn(n.y, -s.y);
                float d2 = __fadd_rn(__fmul_rn(dx, dx), __fmul_rn(dy, dy));
                ull ck = ((ull)__float_as_uint(d2) << 32) | (uint32_t)idx;
                key = (ck < key) ? ck : key;
            }
            key = bfly_min(key);

            mbar_wait_cta(mb_keys, b & 1);
            ull kk = (lane < 31) ? keys[b & 1][lane] : key;

            // ---- speculative fixup: lane j owns sample 32b+j ----
            const float2 s2 = samps[32 * b + lane];
            const float sx = s2.x, sy = s2.y;
            float bd2 = __uint_as_float((uint32_t)(kk >> 32));
            float2 f  = nodes_s[(uint32_t)kk];
            float cx, cy;
            steer(f.x, f.y, sx, sy, bd2, cx, cy);

            while (true) {
                cand[lane] = make_float2(cx, cy);
                __syncwarp();
                float vmin = INF; int vl = 0;
                #pragma unroll
                for (int l = 0; l < 31; l++) {
                    float2 c = cand[l];
                    float dx = __fadd_rn(sx, -c.x), dy = __fadd_rn(sy, -c.y);
                    float cd2 = __fadd_rn(__fmul_rn(dx, dx), __fmul_rn(dy, dy));
                    if (l < lane && cd2 < vmin) { vmin = cd2; vl = l; }
                }
                unsigned mask = __ballot_sync(FULLMASK, vmin < bd2);  // strict <
                if (!mask) break;
                int F2 = __ffs((int)mask) - 1;       // first violator: vs finals only
                if (lane == F2) {
                    bd2 = vmin;
                    float2 c = cand[vl];
                    steer(c.x, c.y, sx, sy, bd2, cx, cy);
                }
            }
            nodes_s[32 * b + 1 + lane] = make_float2(cx, cy);
            mbar_arrive_cta(mb_nodes);               // all 32 lanes, count 32
        }
    }

    __syncthreads();
    CLUSTER_ARRIVE();
    CLUSTER_WAIT();

    if (crank == 0) {
        const float* ns = reinterpret_cast<const float*>(nodes_s);
        for (int i = tid; i < 2 * NNODES; i += NTHREADS)
            out[i] = ns[i];
    }
}

extern "C" void kernel_launch(void* const* d_in, const int* in_sizes, int n_in,
                              void* d_out, int out_size)
{
    const float* state = (const float*)d_in[0];
    const float* goal  = (const float*)d_in[1];
    const float* u     = (const float*)d_in[2];
    const float* r     = (const float*)d_in[3];
    float* out = (float*)d_out;

    cudaFuncSetAttribute(rrt_kernel,
                         cudaFuncAttributeMaxDynamicSharedMemorySize,
                         (int)SMEM_BYTES);
    rrt_kernel<<<CSIZE, NTHREADS, SMEM_BYTES>>>(state, goal, u, r, out);
}

// round 6
// speedup vs baseline: 3.5759x; 1.2189x over previous
#include <cuda_runtime.h>
#include <cstdint>

typedef unsigned long long ull;
#define FULLMASK 0xffffffffu

constexpr int MAX_ITER = 8192;
constexpr int NNODES   = MAX_ITER + 1;   // 8193
constexpr int NBLK     = 256;            // 32 iterations per block
constexpr int NTHREADS = 1024;           // 32 warps
constexpr int CSIZE    = 8;
constexpr int SERIAL_WARP = 31;

constexpr int NODES_PAD = 8194;
constexpr int NSLOT_PAD = 34;            // 0..30 = samples, 31/32 = sample-31 halves

// per-CTA smem layout:
//   nodes float2[8194] | samps float2[8192] | bests ull[4][8][34] | keys ull[2][32]
//   cand float2[32]    | mbars ull[6] (0=nodes, 1=keys, 2..5=bests objs)
constexpr size_t OFF_SAMPS = (size_t)NODES_PAD * sizeof(float2);
constexpr size_t OFF_BESTS = OFF_SAMPS + (size_t)MAX_ITER * sizeof(float2);
constexpr size_t OFF_KEYS  = OFF_BESTS + 4ull * CSIZE * NSLOT_PAD * sizeof(ull);
constexpr size_t OFF_CAND  = OFF_KEYS + 2ull * 32 * sizeof(ull);
constexpr size_t OFF_MBARS = OFF_CAND + 32ull * sizeof(float2);
constexpr size_t SMEM_BYTES = OFF_MBARS + 6ull * sizeof(ull);

constexpr ull KEY_INF = ((ull)0x7f800000u << 32);

__device__ __forceinline__ uint32_t smem_u32(const void* p) {
    return (uint32_t)__cvta_generic_to_shared(p);
}
__device__ __forceinline__ uint32_t my_ctarank() {
    uint32_t r; asm("mov.u32 %0, %%cluster_ctarank;" : "=r"(r)); return r;
}
__device__ __forceinline__ uint32_t mapa_u32(uint32_t laddr, uint32_t rank) {
    uint32_t r; asm("mapa.shared::cluster.u32 %0, %1, %2;" : "=r"(r) : "r"(laddr), "r"(rank));
    return r;
}
__device__ __forceinline__ void st_cluster_u64(uint32_t raddr, ull v) {
    asm volatile("st.shared::cluster.u64 [%0], %1;" :: "r"(raddr), "l"(v) : "memory");
}
__device__ __forceinline__ void mbar_init(uint32_t a, uint32_t cnt) {
    asm volatile("mbarrier.init.shared.b64 [%0], %1;" :: "r"(a), "r"(cnt) : "memory");
}
__device__ __forceinline__ void mbar_arrive_cta(uint32_t a) {
    asm volatile("mbarrier.arrive.release.cta.shared::cta.b64 _, [%0];" :: "r"(a) : "memory");
}
__device__ __forceinline__ void mbar_arrive_cluster_remote(uint32_t raddr) {
    asm volatile("mbarrier.arrive.release.cluster.shared::cluster.b64 _, [%0];"
                 :: "r"(raddr) : "memory");
}
__device__ __forceinline__ void mbar_wait_cta(uint32_t a, uint32_t phase) {
    asm volatile(
        "{\n\t.reg .pred P;\n\t"
        "WL_%=:\n\t"
        "mbarrier.try_wait.parity.acquire.cta.shared::cta.b64 P, [%0], %1, 0x989680;\n\t"
        "@P bra.uni WD_%=;\n\t"
        "bra.uni WL_%=;\n\t"
        "WD_%=:\n\t}"
        :: "r"(a), "r"(phase) : "memory");
}
__device__ __forceinline__ void mbar_wait_cluster(uint32_t a, uint32_t phase) {
    asm volatile(
        "{\n\t.reg .pred P;\n\t"
        "WL_%=:\n\t"
        "mbarrier.try_wait.parity.acquire.cluster.shared::cta.b64 P, [%0], %1, 0x989680;\n\t"
        "@P bra.uni WD_%=;\n\t"
        "bra.uni WL_%=;\n\t"
        "WD_%=:\n\t}"
        :: "r"(a), "r"(phase) : "memory");
}
#define CLUSTER_ARRIVE() asm volatile("barrier.cluster.arrive.aligned;" ::: "memory")
#define CLUSTER_WAIT()   asm volatile("barrier.cluster.wait.aligned;"   ::: "memory")

__device__ __forceinline__ ull bfly_min(ull key) {
    #pragma unroll
    for (int o = 16; o > 0; o >>= 1) {
        ull other = __shfl_xor_sync(FULLMASK, key, o);
        key = (other < key) ? other : key;
    }
    return key;
}

// exact-rounding steer: new = from + (sample-from)*scale, scale = dist>5 ? 5/dist : 1
__device__ __forceinline__ void steer(float fx, float fy, float sx, float sy, float d2,
                                      float& ox, float& oy) {
    float dist = __fsqrt_rn(__fadd_rn(d2, 1e-12f));
    float q    = __fdiv_rn(5.0f, dist);
    float sc   = (dist > 5.0f) ? q : 1.0f;
    ox = __fadd_rn(fx, __fmul_rn(__fadd_rn(sx, -fx), sc));
    oy = __fadd_rn(fy, __fmul_rn(__fadd_rn(sy, -fy), sc));
}

// per-lane scan partial over tiles t = t0, t0+tstep, ... while 64t <= bound.
// sentinel (+inf) nodes make over-reads harmless; tail race with the serial
// warp's STS.64 is tear-free (8B aligned) and value-correct either way.
__device__ __forceinline__ ull scan_part(const float2* __restrict__ nodes_s, float2 s,
                                         int bound, int t0, int tstep, int lane) {
    const float INF = __int_as_float(0x7f800000);
    float bd2 = INF; int bidx = 0;
    for (int t = t0; 64 * t <= bound; t += tstep) {
        int idx = 64 * t + 2 * lane;
        float4 n = *reinterpret_cast<const float4*>(&nodes_s[idx]);
        float dxa = __fadd_rn(n.x, -s.x), dya = __fadd_rn(n.y, -s.y);
        float d2a = __fadd_rn(__fmul_rn(dxa, dxa), __fmul_rn(dya, dya));
        float dxb = __fadd_rn(n.z, -s.x), dyb = __fadd_rn(n.w, -s.y);
        float d2b = __fadd_rn(__fmul_rn(dxb, dxb), __fmul_rn(dyb, dyb));
        float m  = fminf(d2a, d2b);
        int   mi = (d2a <= d2b) ? idx : idx + 1;     // first-index tiebreak in pair
        if (m < bd2) { bd2 = m; bidx = mi; }         // strict <: earliest kept
    }
    return ((ull)__float_as_uint(bd2) << 32) | (uint32_t)bidx;
}

__global__ void __launch_bounds__(NTHREADS, 1) __cluster_dims__(CSIZE, 1, 1)
rrt_kernel(const float* __restrict__ state,
           const float* __restrict__ goal,
           const float* __restrict__ u,
           const float* __restrict__ r,
           float* __restrict__ out)
{
    extern __shared__ char smem_raw[];
    float2* nodes_s = (float2*)smem_raw;
    float2* samps   = (float2*)(smem_raw + OFF_SAMPS);
    ull (*bests)[CSIZE][NSLOT_PAD] = (ull (*)[CSIZE][NSLOT_PAD])(smem_raw + OFF_BESTS);
    ull (*keys)[32] = (ull (*)[32])(smem_raw + OFF_KEYS);
    float2* cand    = (float2*)(smem_raw + OFF_CAND);
    ull* mbars      = (ull*)(smem_raw + OFF_MBARS);

    const int tid  = threadIdx.x;
    const int lane = tid & 31;
    const int warp = tid >> 5;
    const uint32_t crank = my_ctarank();
    const float INF = __int_as_float(0x7f800000);

    const uint32_t mb_nodes = smem_u32(&mbars[0]);
    const uint32_t mb_keys  = smem_u32(&mbars[1]);
    const uint32_t mb_bests0 = smem_u32(&mbars[2]);   // objects 0..3 at +8*obj

    // ---- init ----
    for (int i = tid; i < NODES_PAD; i += NTHREADS)
        nodes_s[i] = make_float2(INF, INF);
    const float gx = goal[0], gy = goal[1];
    for (int i = tid; i < MAX_ITER; i += NTHREADS) {
        float ui = u[i];
        float sx = __fmul_rn(r[2 * i],     200.0f);
        float sy = __fmul_rn(r[2 * i + 1], 200.0f);
        if (ui < 0.1f) { sx = gx; sy = gy; }
        samps[i] = make_float2(sx, sy);
    }
    if (tid == 0) {
        nodes_s[0] = make_float2(state[0], state[1]);
        mbar_init(mb_nodes, 32);                   // serial warp lanes
        mbar_init(mb_keys, 31);                    // scan warps' lane-0
        for (int o = 0; o < 4; o++)                // 33 slots x 8 src CTAs
            mbar_init(mb_bests0 + 8 * o, 33 * CSIZE);
    }
    __syncthreads();
    CLUSTER_ARRIVE();
    CLUSTER_WAIT();

    for (int b = 0; b < NBLK; b++) {
        if (warp != SERIAL_WARP && b > 0) mbar_wait_cta(mb_nodes, (b - 1) & 1);
        // partials for block b were sent during block b-2: a full block of slack
        if (b >= 2) mbar_wait_cluster(mb_bests0 + 8 * ((b - 2) & 3), ((b - 2) >> 2) & 1);

        if (warp != SERIAL_WARP) {
            // ===== delta(64 newest) + merge for sample 32b+warp =====
            const float2 s = samps[32 * b + warp];
            ull key = KEY_INF;
            if (b >= 2 && lane < CSIZE) key = bests[(b - 2) & 3][lane][warp];
            #pragma unroll
            for (int w = 0; w < 2; w++) {
                int idx = 32 * b - 63 + 32 * w + lane;
                if (idx >= 0) {
                    float2 n = nodes_s[idx];
                    float dx = __fadd_rn(n.x, -s.x), dy = __fadd_rn(n.y, -s.y);
                    float d2 = __fadd_rn(__fmul_rn(dx, dx), __fmul_rn(dy, dy));
                    ull ck = ((ull)__float_as_uint(d2) << 32) | (uint32_t)idx;
                    key = (ck < key) ? ck : key;
                }
            }
            key = bfly_min(key);
            if (lane == 0) keys[b & 1][warp] = key;
            if (lane == 0) mbar_arrive_cta(mb_keys);

            // ===== overlapped scan + cross-CTA send for block b+2 =====
            if (b < NBLK - 2) {
                const int obj = b & 3;
                ull pk = scan_part(nodes_s, samps[32 * (b + 2) + warp],
                                   32 * b, (int)crank, CSIZE, lane);
                pk = bfly_min(pk);
                if (lane < CSIZE) {
                    uint32_t la = smem_u32(&bests[obj][crank][warp]);
                    st_cluster_u64(mapa_u32(la, (uint32_t)lane), pk);
                    mbar_arrive_cluster_remote(mapa_u32(mb_bests0 + 8 * obj, (uint32_t)lane));
                }
                if (warp == 29 || warp == 30) {       // sample 31 split in halves
                    int t0 = (warp == 29) ? (int)crank : (int)crank + CSIZE;
                    ull pk2 = scan_part(nodes_s, samps[32 * (b + 2) + 31],
                                        32 * b, t0, 2 * CSIZE, lane);
                    pk2 = bfly_min(pk2);
                    int slot = (warp == 29) ? 31 : 32;
                    if (lane < CSIZE) {
                        uint32_t la = smem_u32(&bests[obj][crank][slot]);
                        st_cluster_u64(mapa_u32(la, (uint32_t)lane), pk2);
                        mbar_arrive_cluster_remote(mapa_u32(mb_bests0 + 8 * obj, (uint32_t)lane));
                    }
                }
            }
        } else {
            // ===== serial warp =====
            // delta + merge for sample 32b+31 (slots 31,32 across 16 lanes)
            const float2 s = samps[32 * b + 31];
            ull key = KEY_INF;
            if (b >= 2) {
                if (lane < CSIZE)            key = bests[(b - 2) & 3][lane][31];
                else if (lane < 2 * CSIZE)   key = bests[(b - 2) & 3][lane - CSIZE][32];
            }
            #pragma unroll
            for (int w = 0; w < 2; w++) {
                int idx = 32 * b - 63 + 32 * w + lane;
                if (idx >= 0) {
                    float2 n = nodes_s[idx];
                    float dx = __fadd_rn(n.x, -s.x), dy = __fadd_rn(n.y, -s.y);
                    float d2 = __fadd_rn(__fmul_rn(dx, dx), __fmul_rn(dy, dy));
                    ull ck = ((ull)__float_as_uint(d2) << 32) | (uint32_t)idx;
                    key = (ck < key) ? ck : key;
                }
            }
            key = bfly_min(key);

            mbar_wait_cta(mb_keys, b & 1);
            ull kk = (lane < 31) ? keys[b & 1][lane] : key;

            // ---- speculative fixup: lane j owns sample 32b+j ----
            const float2 s2 = samps[32 * b + lane];
            const float sx = s2.x, sy = s2.y;
            float bd2 = __uint_as_float((uint32_t)(kk >> 32));
            float2 f  = nodes_s[(uint32_t)kk];
            float cx, cy;
            steer(f.x, f.y, sx, sy, bd2, cx, cy);

            while (true) {
                cand[lane] = make_float2(cx, cy);
                __syncwarp();
                float vmin = INF; int vl = 0;
                #pragma unroll
                for (int l = 0; l < 31; l++) {
                    float2 c = cand[l];
                    float dx = __fadd_rn(sx, -c.x), dy = __fadd_rn(sy, -c.y);
                    float cd2 = __fadd_rn(__fmul_rn(dx, dx), __fmul_rn(dy, dy));
                    if (l < lane && cd2 < vmin) { vmin = cd2; vl = l; }
                }
                unsigned mask = __ballot_sync(FULLMASK, vmin < bd2);  // strict <
                if (!mask) break;
                int F2 = __ffs((int)mask) - 1;       // first violator vs finals only
                if (lane == F2) {
                    bd2 = vmin;
                    float2 c = cand[vl];
                    steer(c.x, c.y, sx, sy, bd2, cx, cy);
                }
            }
            nodes_s[32 * b + 1 + lane] = make_float2(cx, cy);
            if (b < NBLK - 1) mbar_arrive_cta(mb_nodes);   // all 32 lanes
        }
    }

    __syncthreads();
    CLUSTER_ARRIVE();
    CLUSTER_WAIT();

    if (crank == 0) {
        const float* ns = reinterpret_cast<const float*>(nodes_s);
        for (int i = tid; i < 2 * NNODES; i += NTHREADS)
            out[i] = ns[i];
    }
}

extern "C" void kernel_launch(void* const* d_in, const int* in_sizes, int n_in,
                              void* d_out, int out_size)
{
    const float* state = (const float*)d_in[0];
    const float* goal  = (const float*)d_in[1];
    const float* u     = (const float*)d_in[2];
    const float* r     = (const float*)d_in[3];
    float* out = (float*)d_out;

    cudaFuncSetAttribute(rrt_kernel,
                         cudaFuncAttributeMaxDynamicSharedMemorySize,
                         (int)SMEM_BYTES);
    rrt_kernel<<<CSIZE, NTHREADS, SMEM_BYTES>>>(state, goal, u, r, out);
}